// round 13
// baseline (speedup 1.0000x reference)
#include <cuda_runtime.h>

#define FULL_MASK 0xffffffffu

// ---- device scratch (no allocations allowed; zero-initialized at load,
//      and restored to zero by the finalizing block every launch) ----
__device__ float g_stage[1024];   // per-(image,class) partial sums
__device__ int   g_count;         // completed-block counter

// ============================================================================
// Packed f32x2 helpers
// ============================================================================
__device__ __forceinline__ float2 f2fma(float2 a, float2 b, float2 c) {
    float2 d;
    asm("fma.rn.f32x2 %0, %1, %2, %3;"
        : "=l"(*reinterpret_cast<unsigned long long*>(&d))
        : "l"(*reinterpret_cast<unsigned long long*>(&a)),
          "l"(*reinterpret_cast<unsigned long long*>(&b)),
          "l"(*reinterpret_cast<unsigned long long*>(&c)));
    return d;
}
__device__ __forceinline__ float2 f2mul(float2 a, float2 b) {
    float2 d;
    asm("mul.rn.f32x2 %0, %1, %2;"
        : "=l"(*reinterpret_cast<unsigned long long*>(&d))
        : "l"(*reinterpret_cast<unsigned long long*>(&a)),
          "l"(*reinterpret_cast<unsigned long long*>(&b)));
    return d;
}
__device__ __forceinline__ float2 cmul(float2 a, float2 b) {
    return { a.x * b.x - a.y * b.y, a.x * b.y + a.y * b.x };
}

// ============================================================================
// Layout: amp(lane, r) ; register bits r[0..3] = qubits {0,1,3,6}
//                        lane bits  [0..4]    = qubits {2,4,5,7,8}
// ============================================================================

template<int TB>
__device__ __forceinline__ void ry_reg(float2* a, float c, float s) {
    const float2 c2 = { c, c }, s2 = { s, s }, ns2 = { -s, -s };
    #pragma unroll
    for (int r0 = 0; r0 < 16; ++r0) {
        if (r0 & TB) continue;
        float2 a0 = a[r0], a1 = a[r0 | TB];
        a[r0]      = f2fma(a1, ns2, f2mul(a0, c2));
        a[r0 | TB] = f2fma(a0, s2,  f2mul(a1, c2));
    }
}

template<int CB, int TB>
__device__ __forceinline__ void cx_rr(float2* a) {   // pure register permutation (free)
    #pragma unroll
    for (int r0 = 0; r0 < 16; ++r0) {
        if ((r0 & CB) && !(r0 & TB)) {
            float2 t = a[r0]; a[r0] = a[r0 | TB]; a[r0 | TB] = t;
        }
    }
}

template<int CB, int LM>
__device__ __forceinline__ void cx_rl(float2* a) {   // reg control, lane target: 8 regs shuffle
    #pragma unroll
    for (int r = 0; r < 16; ++r) {
        if (r & CB) {
            float2 p;
            p.x = __shfl_xor_sync(FULL_MASK, a[r].x, LM);
            p.y = __shfl_xor_sync(FULL_MASK, a[r].y, LM);
            a[r] = p;
        }
    }
}

template<int LMC, int TB>
__device__ __forceinline__ void cx_lr(float2* a, int lane) {  // lane control, reg target
    const bool p = (lane & LMC) != 0;
    #pragma unroll
    for (int r0 = 0; r0 < 16; ++r0) {
        if (r0 & TB) continue;
        if (p) { float2 t = a[r0]; a[r0] = a[r0 | TB]; a[r0 | TB] = t; }
    }
}

// Fused pair of CX gates compiled to one shfl.idx pass:
//   src0 applies to regs with bit RB = 0, src1 to regs with bit RB = 1.
template<int RB>
__device__ __forceinline__ void cx_fused_ll(float2* a, int src0, int src1) {
    #pragma unroll
    for (int r = 0; r < 16; ++r) {
        const int s = (r & RB) ? src1 : src0;
        a[r].x = __shfl_sync(FULL_MASK, a[r].x, s);
        a[r].y = __shfl_sync(FULL_MASK, a[r].y, s);
    }
}

// Rx pair update: n0 = co*t0 - i si*t1 ; n1 = co*t1 - i si*t0
__device__ __forceinline__ void crx_pair(float2& t0, float2& t1, float co, float si) {
    float2 n0 = { co * t0.x + si * t1.y, co * t0.y - si * t1.x };
    float2 n1 = { co * t1.x + si * t0.y, co * t1.y - si * t0.x };
    t0 = n0; t1 = n1;
}

template<int CB, int TB>
__device__ __forceinline__ void crx_rr(float2* a, float co, float si) {
    #pragma unroll
    for (int r0 = 0; r0 < 16; ++r0) {
        if ((r0 & CB) && !(r0 & TB)) crx_pair(a[r0], a[r0 | TB], co, si);
    }
}

// ============================================================================
// Single fused kernel. Per-block table prep runs WITHOUT a leading barrier;
// encoding + product state + ring CX use only per-lane data (conv1 RZ diagonal
// factored into per-lane complex tables), so the single __syncthreads sits
// just before pool1 and the prep latency is hidden behind ~400 cycles of work.
// One warp per patch, 4 warps/block (block uniform in image b).
// ============================================================================
__global__ void __launch_bounds__(128, 9)
qcnn_kernel(const float* __restrict__ x, const float* __restrict__ w,
            const float* __restrict__ fc_w, const float* __restrict__ fc_b,
            float* __restrict__ out, int K, int ncls, int nblocks, int nout) {
    __shared__ float  s_wc[42], s_ws[42];
    __shared__ float2 s_d2[16];
    __shared__ float2 s_pA[4], s_pB[4], s_pC[4];
    __shared__ float2 s_mry0, s_mry6, s_m41;
    __shared__ float  s_acc[16];
    __shared__ int    s_rank;

    const int tid  = threadIdx.x;
    const int lane = tid & 31;

    // ---- per-block table prep: <=1 __sincosf per thread, NO barrier here ----
    if (tid < 16) s_acc[tid] = 0.f;
    if (tid < 42) {
        float s, c; __sincosf(0.5f * w[tid], &s, &c);
        s_wc[tid] = c; s_ws[tid] = s;
    } else if (tid < 58) {          // conv2 RZ diag on {q0:b0, q3:b2, q6:b3}
        const int r = tid - 42;
        const float ang = 0.5f * (((r & 1) ? w[27] : -w[27]) + ((r & 4) ? w[28] : -w[28])
                                + ((r & 8) ? w[29] : -w[29]));
        float s, c; __sincosf(ang, &s, &c);
        s_d2[r] = { c, s };
    } else if (tid == 58) {
        float s, c; __sincosf(0.5f * (w[34] + w[36]), &s, &c); s_mry0 = { c, s };
    } else if (tid == 59) {
        float s, c; __sincosf(0.5f * (w[35] + w[37]), &s, &c); s_mry6 = { c, s };
    } else if (tid == 60) {
        float s, c; __sincosf(w[41], &s, &c); s_m41 = { c, s };   // FULL angle
    } else if (tid >= 64 && tid < 68) {   // pool1 A: bit1 -> q1 (w18), bit0 -> q2 (w19)
        const int i = tid - 64;
        float s, c; __sincosf(0.5f * (((i >> 1) & 1) * w[18] + (i & 1) * w[19]), &s, &c);
        s_pA[i] = { c, s };
    } else if (tid >= 68 && tid < 72) {   // pool1 B: bit0 -> q4 (w20), bit1 -> q5 (w21)
        const int i = tid - 68;
        float s, c; __sincosf(0.5f * ((i & 1) * w[20] + ((i >> 1) & 1) * w[21]), &s, &c);
        s_pB[i] = { c, s };
    } else if (tid >= 72 && tid < 76) {   // pool1 C: bit0 -> q7 (w22), bit1 -> q8 (w23)
        const int i = tid - 72;
        float s, c; __sincosf(0.5f * ((i & 1) * w[22] + ((i >> 1) & 1) * w[23]), &s, &c);
        s_pC[i] = { c, s };
    }

    // ---- per-warp circuit (everything below until pool1 is shared-free) ----
    const int warp = (blockIdx.x << 2) | (tid >> 5);
    const int b   = warp / 676;
    const int rem = warp - b * 676;
    const int pi  = rem / 26;
    const int pj  = rem - pi * 26;
    const float* img = x + b * 784;

    // w[0..17] live in one 128B line; uniform broadcast loads
    const float HALF_PI = 1.57079632679489662f;
    float cr[4], sr[4], cl[5], sl[5];
    // register qubits: q0(0,0) q1(0,1) q3(1,0) q6(2,0)
    __sincosf(img[(pi + 0) * 28 + (pj + 0)] * HALF_PI + 0.5f * __ldg(w + 0), &sr[0], &cr[0]);
    __sincosf(img[(pi + 0) * 28 + (pj + 1)] * HALF_PI + 0.5f * __ldg(w + 1), &sr[1], &cr[1]);
    __sincosf(img[(pi + 1) * 28 + (pj + 0)] * HALF_PI + 0.5f * __ldg(w + 3), &sr[2], &cr[2]);
    __sincosf(img[(pi + 2) * 28 + (pj + 0)] * HALF_PI + 0.5f * __ldg(w + 6), &sr[3], &cr[3]);
    // lane qubits: q2(0,2) q4(1,1) q5(1,2) q7(2,1) q8(2,2)
    __sincosf(img[(pi + 0) * 28 + (pj + 2)] * HALF_PI + 0.5f * __ldg(w + 2), &sl[0], &cl[0]);
    __sincosf(img[(pi + 1) * 28 + (pj + 1)] * HALF_PI + 0.5f * __ldg(w + 4), &sl[1], &cl[1]);
    __sincosf(img[(pi + 1) * 28 + (pj + 2)] * HALF_PI + 0.5f * __ldg(w + 5), &sl[2], &cl[2]);
    __sincosf(img[(pi + 2) * 28 + (pj + 1)] * HALF_PI + 0.5f * __ldg(w + 7), &sl[3], &cl[3]);
    __sincosf(img[(pi + 2) * 28 + (pj + 2)] * HALF_PI + 0.5f * __ldg(w + 8), &sl[4], &cl[4]);

    // conv1 RZ diagonal, per-lane: lane-bit phase + factored register-bit phases
    const float w9v  = __ldg(w + 9),  w10v = __ldg(w + 10), w11v = __ldg(w + 11);
    const float w12v = __ldg(w + 12), w13v = __ldg(w + 13), w14v = __ldg(w + 14);
    const float w15v = __ldg(w + 15), w16v = __ldg(w + 16), w17v = __ldg(w + 17);
    float cA, sA, cB, sB, cC, sC, cD, sD;
    __sincosf(0.5f * (w9v + w10v),  &sA, &cA);   // (q0,q1) phase, equal bits
    __sincosf(0.5f * (w9v - w10v),  &sB, &cB);   // (q0,q1) phase, mixed bits
    __sincosf(0.5f * (w12v + w15v), &sC, &cC);   // (q3,q6) phase, equal bits
    __sincosf(0.5f * (w12v - w15v), &sD, &cD);   // (q3,q6) phase, mixed bits
    float angl = ((lane & 1)  ? w11v : -w11v) + ((lane & 2)  ? w13v : -w13v)
               + ((lane & 4)  ? w14v : -w14v) + ((lane & 8)  ? w16v : -w16v)
               + ((lane & 16) ? w17v : -w17v);
    float cdl, sdl; __sincosf(0.5f * angl, &sdl, &cdl);

    float Lp = ((lane & 1)  ? sl[0] : cl[0]) * ((lane & 2)  ? sl[1] : cl[1]);
    Lp *= ((lane & 4)  ? sl[2] : cl[2]);
    Lp *= ((lane & 8)  ? sl[3] : cl[3]);
    Lp *= ((lane & 16) ? sl[4] : cl[4]);

    const float p01[4] = { cr[0]*cr[1], sr[0]*cr[1], cr[0]*sr[1], sr[0]*sr[1] };
    const float p23[4] = { cr[2]*cr[3], sr[2]*cr[3], cr[2]*sr[3], sr[2]*sr[3] };

    // complex amplitude tables: amplitude * RZ phase  (j bits: b0->w9, b1->w10)
    float2 P01c[4], P23c[4];
    P01c[0] = { p01[0] * cA, -p01[0] * sA };
    P01c[1] = { p01[1] * cB,  p01[1] * sB };
    P01c[2] = { p01[2] * cB, -p01[2] * sB };
    P01c[3] = { p01[3] * cA,  p01[3] * sA };
    P23c[0] = { p23[0] * cC, -p23[0] * sC };
    P23c[1] = { p23[1] * cD,  p23[1] * sD };
    P23c[2] = { p23[2] * cD, -p23[2] * sD };
    P23c[3] = { p23[3] * cC,  p23[3] * sC };

    const float2 LD = { Lp * cdl, Lp * sdl };
    float2 t4[4];
    #pragma unroll
    for (int j = 0; j < 4; ++j) t4[j] = cmul(LD, P01c[j]);

    float2 a[16];
    #pragma unroll
    for (int r = 0; r < 16; ++r) a[r] = cmul(t4[r & 3], P23c[r >> 2]);

    // ---- ring CX (q -> q+1 mod 9) under the remap (shared-free) ----
    cx_rr<1, 2>(a);               // (0,1)  free
    cx_rl<2, 1>(a);               // (1,2)
    cx_lr<1, 4>(a, lane);         // (2,3)
    {   // (3,4)+(4,5) fused
        const int base = (lane & 2) ? (lane ^ 4) : lane;
        cx_fused_ll<4>(a, base, base ^ 2);
    }
    cx_lr<4, 8>(a, lane);         // (5,6)
    {   // (6,7)+(7,8) fused
        const int base = (lane & 8) ? (lane ^ 16) : lane;
        cx_fused_ll<8>(a, base, base ^ 8);
    }
    cx_lr<16, 1>(a, lane);        // (8,0)

    __syncthreads();   // prep tables ready; latency hidden behind the above

    // ---- pool1: 6 CRX merged into 3 passes ----
    {   // A: target q0 (bit0); controls q1 = reg bit1, q2 = lane bit0
        const float2 cA0 = s_pA[lane & 1];
        const float2 cA1 = s_pA[2 + (lane & 1)];
        #pragma unroll
        for (int r0 = 0; r0 < 16; r0 += 2) {
            const float2 cs = (r0 & 2) ? cA1 : cA0;
            crx_pair(a[r0], a[r0 + 1], cs.x, cs.y);
        }
    }
    {   // B: target q3 (bit2); controls q4 = lane bit1, q5 = lane bit2
        const float2 cs = s_pB[(lane >> 1) & 3];
        #pragma unroll
        for (int r0 = 0; r0 < 16; ++r0)
            if (!(r0 & 4)) crx_pair(a[r0], a[r0 | 4], cs.x, cs.y);
    }
    {   // C: target q6 (bit3); controls q7 = lane bit3, q8 = lane bit4
        const float2 cs = s_pC[(lane >> 3) & 3];
        #pragma unroll
        for (int r0 = 0; r0 < 8; ++r0) crx_pair(a[r0], a[r0 | 8], cs.x, cs.y);
    }

    // ---- conv2 on {0,3,6}: register-local ----
    ry_reg<1>(a, s_wc[24], s_ws[24]);
    ry_reg<4>(a, s_wc[25], s_ws[25]);
    ry_reg<8>(a, s_wc[26], s_ws[26]);
    #pragma unroll
    for (int r = 0; r < 16; ++r) a[r] = cmul(a[r], s_d2[r]);
    cx_rr<1, 4>(a);            // (0,3)
    cx_rr<4, 8>(a);            // (3,6)
    cx_rr<8, 1>(a);            // (6,0)
    ry_reg<1>(a, s_wc[30], s_ws[30]);
    // RZ(3, w31) dropped: commutes to the end, unobservable on q0.

    // ---- pool2 ----
    crx_rr<4, 1>(a, s_wc[32], s_ws[32]);   // (3,0)
    crx_rr<4, 8>(a, s_wc[33], s_ws[33]);   // (3,6)
    {
        const float2 m0 = s_mry0; ry_reg<1>(a, m0.x, m0.y);   // RY(0, w34+w36)
        const float2 m6 = s_mry6; ry_reg<8>(a, m6.x, m6.y);   // RY(6, w35+w37)
    }

    // ---- conv3 ----
    cx_rr<1, 8>(a);            // (0,6)
    {   // RZ(0, w38) on register bit 0
        const float cz = s_wc[38], sz = s_ws[38];
        #pragma unroll
        for (int r = 0; r < 16; ++r) {
            const float d = (r & 1) ? sz : -sz;
            const float2 v = a[r];
            a[r] = { cz * v.x - d * v.y, cz * v.y + d * v.x };
        }
    }
    // RZ(6, w39) dropped.

    // ---- pool3 CRX(6,0) ----
    crx_rr<8, 1>(a, s_wc[40], s_ws[40]);
    // Final RY(0, w41) folded into measurement (Bloch rotation below).

    // ---- <X>,<Y>,<Z> on qubit 0 (register bit 0), pre-RY(w41) ----
    float zr = 0.f, zi = 0.f, ez = 0.f;
    #pragma unroll
    for (int r0 = 0; r0 < 16; r0 += 2) {
        float2 a0 = a[r0], a1 = a[r0 + 1];
        zr += a0.x * a1.x + a0.y * a1.y;
        zi += a0.x * a1.y - a0.y * a1.x;
        ez += a0.x * a0.x + a0.y * a0.y - a1.x * a1.x - a1.y * a1.y;
    }
    #pragma unroll
    for (int off = 16; off; off >>= 1) {
        zr += __shfl_xor_sync(FULL_MASK, zr, off);
        zi += __shfl_xor_sync(FULL_MASK, zi, off);
        ez += __shfl_xor_sync(FULL_MASK, ez, off);
    }

    // ---- fused FC: lanes 0..ncls-1 stage class partials in smem ----
    if (lane < ncls) {
        // Bloch rotation for RY(w41): ex' = c*ex + s*ez ; ez' = -s*ex + c*ez ; ey' = ey
        const float2 m = s_m41;
        const float ex0 = 2.f * zr, ey = 2.f * zi;
        const float ex = m.x * ex0 + m.y * ez;
        const float ezf = -m.y * ex0 + m.x * ez;
        const float* wrow = fc_w + lane * K + rem * 3;
        const float partial = ex * wrow[0] + ey * wrow[1] + ezf * wrow[2];
        atomicAdd(&s_acc[lane], partial);
    }
    __syncthreads();

    // ---- stage into device scratch, then last-finishing block finalizes ----
    if (tid < ncls) {
        const int b_blk = (blockIdx.x << 2) / 676;   // b is block-uniform
        atomicAdd(&g_stage[b_blk * ncls + tid], s_acc[tid]);
        __threadfence();
    }
    __syncthreads();
    if (tid == 0) s_rank = atomicAdd(&g_count, 1);
    __syncthreads();

    if (s_rank == nblocks - 1) {   // all other blocks' stage atomics are visible
        __threadfence();
        for (int i = tid; i < nout; i += blockDim.x) {
            out[i] = g_stage[i] + fc_b[i % ncls];
            g_stage[i] = 0.f;      // restore invariant for next launch/replay
        }
        if (tid == 0) g_count = 0;
    }
}

// ============================================================================
extern "C" void kernel_launch(void* const* d_in, const int* in_sizes, int n_in,
                              void* d_out, int out_size) {
    const float* x    = (const float*)d_in[0];   // (B,1,28,28)
    const float* w    = (const float*)d_in[1];   // (42,)
    const float* fc_w = (const float*)d_in[2];   // (ncls, K)
    const float* fc_b = (const float*)d_in[3];   // (ncls,)
    float* out = (float*)d_out;

    const int B      = in_sizes[0] / (28 * 28);
    const int npatch = B * 26 * 26;              // 676 % 4 == 0 -> exact grid
    const int ncls   = in_sizes[3];
    const int K      = in_sizes[2] / ncls;
    const int nblocks = npatch / 4;

    qcnn_kernel<<<nblocks, 128>>>(x, w, fc_w, fc_b, out, K, ncls, nblocks, B * ncls);
}

// round 14
// speedup vs baseline: 1.0374x; 1.0374x over previous
#include <cuda_runtime.h>

#define FULL_MASK 0xffffffffu

// ---- device scratch (no allocations allowed; zero-initialized at load,
//      and restored to zero by the finalizing block every launch) ----
__device__ float g_stage[1024];   // per-(image,class) partial sums
__device__ int   g_count;         // completed-block counter

// ============================================================================
// Packed f32x2 helpers
// ============================================================================
__device__ __forceinline__ float2 f2fma(float2 a, float2 b, float2 c) {
    float2 d;
    asm("fma.rn.f32x2 %0, %1, %2, %3;"
        : "=l"(*reinterpret_cast<unsigned long long*>(&d))
        : "l"(*reinterpret_cast<unsigned long long*>(&a)),
          "l"(*reinterpret_cast<unsigned long long*>(&b)),
          "l"(*reinterpret_cast<unsigned long long*>(&c)));
    return d;
}
__device__ __forceinline__ float2 f2mul(float2 a, float2 b) {
    float2 d;
    asm("mul.rn.f32x2 %0, %1, %2;"
        : "=l"(*reinterpret_cast<unsigned long long*>(&d))
        : "l"(*reinterpret_cast<unsigned long long*>(&a)),
          "l"(*reinterpret_cast<unsigned long long*>(&b)));
    return d;
}
__device__ __forceinline__ float2 cmul(float2 a, float2 b) {
    return { a.x * b.x - a.y * b.y, a.x * b.y + a.y * b.x };
}

// predicated swap of two float2 (compiles to SELs)
__device__ __forceinline__ void cswap2(float2& u, float2& v, bool p) {
    float2 t0 = u, t1 = v;
    u = p ? t1 : t0;
    v = p ? t0 : t1;
}

// ============================================================================
// Layout: amp(lane, r) ; register bits r[0..3] = qubits {0,1,3,6}
//                        lane bits  [0..4]    = qubits {2,4,5,7,8}
// ============================================================================

template<int TB>
__device__ __forceinline__ void ry_reg(float2* a, float c, float s) {
    const float2 c2 = { c, c }, s2 = { s, s }, ns2 = { -s, -s };
    #pragma unroll
    for (int r0 = 0; r0 < 16; ++r0) {
        if (r0 & TB) continue;
        float2 a0 = a[r0], a1 = a[r0 | TB];
        a[r0]      = f2fma(a1, ns2, f2mul(a0, c2));
        a[r0 | TB] = f2fma(a0, s2,  f2mul(a1, c2));
    }
}

template<int CB, int TB>
__device__ __forceinline__ void cx_rr(float2* a) {   // pure register permutation (free)
    #pragma unroll
    for (int r0 = 0; r0 < 16; ++r0) {
        if ((r0 & CB) && !(r0 & TB)) {
            float2 t = a[r0]; a[r0] = a[r0 | TB]; a[r0 | TB] = t;
        }
    }
}

// Rx pair update: n0 = co*t0 - i si*t1 ; n1 = co*t1 - i si*t0
__device__ __forceinline__ void crx_pair(float2& t0, float2& t1, float co, float si) {
    float2 n0 = { co * t0.x + si * t1.y, co * t0.y - si * t1.x };
    float2 n1 = { co * t1.x + si * t0.y, co * t1.y - si * t0.x };
    t0 = n0; t1 = n1;
}

template<int CB, int TB>
__device__ __forceinline__ void crx_rr(float2* a, float co, float si) {
    #pragma unroll
    for (int r0 = 0; r0 < 16; ++r0) {
        if ((r0 & CB) && !(r0 & TB)) crx_pair(a[r0], a[r0 | TB], co, si);
    }
}

// ============================================================================
// Single fused kernel. Per-block table prep runs WITHOUT a leading barrier;
// the pre-pool1 section uses only per-lane data. The 9-gate ring CX is
// collapsed into: 3 lane-predicated reg-swap passes + free reg permutation +
// ONE shfl.idx pass (GF(2) composite of the ring permutation).
// One warp per patch, 4 warps/block (block uniform in image b).
// ============================================================================
__global__ void __launch_bounds__(128, 9)
qcnn_kernel(const float* __restrict__ x, const float* __restrict__ w,
            const float* __restrict__ fc_w, const float* __restrict__ fc_b,
            float* __restrict__ out, int K, int ncls, int nblocks, int nout) {
    __shared__ float  s_wc[42], s_ws[42];
    __shared__ float2 s_d2[16];
    __shared__ float2 s_pA[4], s_pB[4], s_pC[4];
    __shared__ float2 s_mry0, s_mry6, s_m41;
    __shared__ float  s_acc[16];
    __shared__ int    s_rank;

    const int tid  = threadIdx.x;
    const int lane = tid & 31;

    // ---- per-block table prep: <=1 __sincosf per thread, NO barrier here ----
    if (tid < 16) s_acc[tid] = 0.f;
    if (tid < 42) {
        float s, c; __sincosf(0.5f * w[tid], &s, &c);
        s_wc[tid] = c; s_ws[tid] = s;
    } else if (tid < 58) {          // conv2 RZ diag on {q0:b0, q3:b2, q6:b3}
        const int r = tid - 42;
        const float ang = 0.5f * (((r & 1) ? w[27] : -w[27]) + ((r & 4) ? w[28] : -w[28])
                                + ((r & 8) ? w[29] : -w[29]));
        float s, c; __sincosf(ang, &s, &c);
        s_d2[r] = { c, s };
    } else if (tid == 58) {
        float s, c; __sincosf(0.5f * (w[34] + w[36]), &s, &c); s_mry0 = { c, s };
    } else if (tid == 59) {
        float s, c; __sincosf(0.5f * (w[35] + w[37]), &s, &c); s_mry6 = { c, s };
    } else if (tid == 60) {
        float s, c; __sincosf(w[41], &s, &c); s_m41 = { c, s };   // FULL angle
    } else if (tid >= 64 && tid < 68) {   // pool1 A: bit1 -> q1 (w18), bit0 -> q2 (w19)
        const int i = tid - 64;
        float s, c; __sincosf(0.5f * (((i >> 1) & 1) * w[18] + (i & 1) * w[19]), &s, &c);
        s_pA[i] = { c, s };
    } else if (tid >= 68 && tid < 72) {   // pool1 B: bit0 -> q4 (w20), bit1 -> q5 (w21)
        const int i = tid - 68;
        float s, c; __sincosf(0.5f * ((i & 1) * w[20] + ((i >> 1) & 1) * w[21]), &s, &c);
        s_pB[i] = { c, s };
    } else if (tid >= 72 && tid < 76) {   // pool1 C: bit0 -> q7 (w22), bit1 -> q8 (w23)
        const int i = tid - 72;
        float s, c; __sincosf(0.5f * ((i & 1) * w[22] + ((i >> 1) & 1) * w[23]), &s, &c);
        s_pC[i] = { c, s };
    }

    // ---- per-warp circuit (everything below until pool1 is shared-free) ----
    const int warp = (blockIdx.x << 2) | (tid >> 5);
    const int b   = warp / 676;
    const int rem = warp - b * 676;
    const int pi  = rem / 26;
    const int pj  = rem - pi * 26;
    const float* img = x + b * 784;

    // w[0..17] live in one 128B line; uniform broadcast loads
    const float HALF_PI = 1.57079632679489662f;
    float cr[4], sr[4], cl[5], sl[5];
    // register qubits: q0(0,0) q1(0,1) q3(1,0) q6(2,0)
    __sincosf(img[(pi + 0) * 28 + (pj + 0)] * HALF_PI + 0.5f * __ldg(w + 0), &sr[0], &cr[0]);
    __sincosf(img[(pi + 0) * 28 + (pj + 1)] * HALF_PI + 0.5f * __ldg(w + 1), &sr[1], &cr[1]);
    __sincosf(img[(pi + 1) * 28 + (pj + 0)] * HALF_PI + 0.5f * __ldg(w + 3), &sr[2], &cr[2]);
    __sincosf(img[(pi + 2) * 28 + (pj + 0)] * HALF_PI + 0.5f * __ldg(w + 6), &sr[3], &cr[3]);
    // lane qubits: q2(0,2) q4(1,1) q5(1,2) q7(2,1) q8(2,2)
    __sincosf(img[(pi + 0) * 28 + (pj + 2)] * HALF_PI + 0.5f * __ldg(w + 2), &sl[0], &cl[0]);
    __sincosf(img[(pi + 1) * 28 + (pj + 1)] * HALF_PI + 0.5f * __ldg(w + 4), &sl[1], &cl[1]);
    __sincosf(img[(pi + 1) * 28 + (pj + 2)] * HALF_PI + 0.5f * __ldg(w + 5), &sl[2], &cl[2]);
    __sincosf(img[(pi + 2) * 28 + (pj + 1)] * HALF_PI + 0.5f * __ldg(w + 7), &sl[3], &cl[3]);
    __sincosf(img[(pi + 2) * 28 + (pj + 2)] * HALF_PI + 0.5f * __ldg(w + 8), &sl[4], &cl[4]);

    // conv1 RZ diagonal, per-lane: lane-bit phase + factored register-bit phases
    const float w9v  = __ldg(w + 9),  w10v = __ldg(w + 10), w11v = __ldg(w + 11);
    const float w12v = __ldg(w + 12), w13v = __ldg(w + 13), w14v = __ldg(w + 14);
    const float w15v = __ldg(w + 15), w16v = __ldg(w + 16), w17v = __ldg(w + 17);
    float cA, sA, cB, sB, cC, sC, cD, sD;
    __sincosf(0.5f * (w9v + w10v),  &sA, &cA);   // (q0,q1) phase, equal bits
    __sincosf(0.5f * (w9v - w10v),  &sB, &cB);   // (q0,q1) phase, mixed bits
    __sincosf(0.5f * (w12v + w15v), &sC, &cC);   // (q3,q6) phase, equal bits
    __sincosf(0.5f * (w12v - w15v), &sD, &cD);   // (q3,q6) phase, mixed bits
    float angl = ((lane & 1)  ? w11v : -w11v) + ((lane & 2)  ? w13v : -w13v)
               + ((lane & 4)  ? w14v : -w14v) + ((lane & 8)  ? w16v : -w16v)
               + ((lane & 16) ? w17v : -w17v);
    float cdl, sdl; __sincosf(0.5f * angl, &sdl, &cdl);

    float Lp = ((lane & 1)  ? sl[0] : cl[0]) * ((lane & 2)  ? sl[1] : cl[1]);
    Lp *= ((lane & 4)  ? sl[2] : cl[2]);
    Lp *= ((lane & 8)  ? sl[3] : cl[3]);
    Lp *= ((lane & 16) ? sl[4] : cl[4]);

    const float p01[4] = { cr[0]*cr[1], sr[0]*cr[1], cr[0]*sr[1], sr[0]*sr[1] };
    const float p23[4] = { cr[2]*cr[3], sr[2]*cr[3], cr[2]*sr[3], sr[2]*sr[3] };

    // complex amplitude tables: amplitude * RZ phase  (j bits: b0->w9, b1->w10)
    float2 P01c[4], P23c[4];
    P01c[0] = { p01[0] * cA, -p01[0] * sA };
    P01c[1] = { p01[1] * cB,  p01[1] * sB };
    P01c[2] = { p01[2] * cB, -p01[2] * sB };
    P01c[3] = { p01[3] * cA,  p01[3] * sA };
    P23c[0] = { p23[0] * cC, -p23[0] * sC };
    P23c[1] = { p23[1] * cD,  p23[1] * sD };
    P23c[2] = { p23[2] * cD, -p23[2] * sD };
    P23c[3] = { p23[3] * cC,  p23[3] * sC };

    const float2 LD = { Lp * cdl, Lp * sdl };
    float2 t4[4];
    #pragma unroll
    for (int j = 0; j < 4; ++j) t4[j] = cmul(LD, P01c[j]);

    float2 a[16];
    #pragma unroll
    for (int r = 0; r < 16; ++r) a[r] = cmul(t4[r & 3], P23c[r >> 2]);

    // ---- ring CX composite (all 9 gates) as one GF(2) permutation ----
    // source bits: s_q0=q0^q8, s_q1=q1^q0^q8, s_qk=qk^q(k-1) (k>=2)
    {
        // stage 1a: lane-conditioned XOR-offset gathers S[u] -> S[u^o], own lane m
        const bool e = (((lane >> 3) ^ (lane >> 4)) & 1) != 0;   // m3^m4 -> flip reg bits {0,1}
        const bool f = (lane & 1) != 0;                          // m0    -> flip reg bit 2
        const bool g = (((lane >> 1) ^ (lane >> 2)) & 1) != 0;   // m1^m2 -> flip reg bit 3
        cswap2(a[0], a[3],  e); cswap2(a[1], a[2],  e);
        cswap2(a[4], a[7],  e); cswap2(a[5], a[6],  e);
        cswap2(a[8], a[11], e); cswap2(a[9], a[10], e);
        cswap2(a[12],a[15], e); cswap2(a[13],a[14], e);
        cswap2(a[0], a[4],  f); cswap2(a[1], a[5],  f);
        cswap2(a[2], a[6],  f); cswap2(a[3], a[7],  f);
        cswap2(a[8], a[12], f); cswap2(a[9], a[13], f);
        cswap2(a[10],a[14], f); cswap2(a[11],a[15], f);
        cswap2(a[0], a[8],  g); cswap2(a[1], a[9],  g);
        cswap2(a[2], a[10], g); cswap2(a[3], a[11], g);
        cswap2(a[4], a[12], g); cswap2(a[5], a[13], g);
        cswap2(a[6], a[14], g); cswap2(a[7], a[15], g);

        // stage 1b: fixed reg permutation (A matrix), stage 2: one shfl.idx pass
        // src lane = lane ^ (l1<<2) ^ (l3<<4) ^ (r1 | r2<<1 | r3<<3)
        const int basev = lane ^ ((lane & 2) << 1) ^ ((lane & 8) << 1);
        const int perm[16] = {0,3,6,5,12,15,10,9,11,8,13,14,7,4,1,2};
        const int csrc[16] = {0,0,1,1,2,2,3,3,8,8,9,9,10,10,11,11};
        float2 bn[16];
        #pragma unroll
        for (int r = 0; r < 16; ++r) {
            const float2 v = a[perm[r]];
            const int src = basev ^ csrc[r];
            bn[r].x = __shfl_sync(FULL_MASK, v.x, src);
            bn[r].y = __shfl_sync(FULL_MASK, v.y, src);
        }
        #pragma unroll
        for (int r = 0; r < 16; ++r) a[r] = bn[r];
    }

    __syncthreads();   // prep tables ready; latency hidden behind the above

    // ---- pool1: 6 CRX merged into 3 passes ----
    {   // A: target q0 (bit0); controls q1 = reg bit1, q2 = lane bit0
        const float2 cA0 = s_pA[lane & 1];
        const float2 cA1 = s_pA[2 + (lane & 1)];
        #pragma unroll
        for (int r0 = 0; r0 < 16; r0 += 2) {
            const float2 cs = (r0 & 2) ? cA1 : cA0;
            crx_pair(a[r0], a[r0 + 1], cs.x, cs.y);
        }
    }
    {   // B: target q3 (bit2); controls q4 = lane bit1, q5 = lane bit2
        const float2 cs = s_pB[(lane >> 1) & 3];
        #pragma unroll
        for (int r0 = 0; r0 < 16; ++r0)
            if (!(r0 & 4)) crx_pair(a[r0], a[r0 | 4], cs.x, cs.y);
    }
    {   // C: target q6 (bit3); controls q7 = lane bit3, q8 = lane bit4
        const float2 cs = s_pC[(lane >> 3) & 3];
        #pragma unroll
        for (int r0 = 0; r0 < 8; ++r0) crx_pair(a[r0], a[r0 | 8], cs.x, cs.y);
    }

    // ---- conv2 on {0,3,6}: register-local ----
    ry_reg<1>(a, s_wc[24], s_ws[24]);
    ry_reg<4>(a, s_wc[25], s_ws[25]);
    ry_reg<8>(a, s_wc[26], s_ws[26]);
    #pragma unroll
    for (int r = 0; r < 16; ++r) a[r] = cmul(a[r], s_d2[r]);
    cx_rr<1, 4>(a);            // (0,3)
    cx_rr<4, 8>(a);            // (3,6)
    cx_rr<8, 1>(a);            // (6,0)
    ry_reg<1>(a, s_wc[30], s_ws[30]);
    // RZ(3, w31) dropped: commutes to the end, unobservable on q0.

    // ---- pool2 ----
    crx_rr<4, 1>(a, s_wc[32], s_ws[32]);   // (3,0)
    crx_rr<4, 8>(a, s_wc[33], s_ws[33]);   // (3,6)
    {
        const float2 m0 = s_mry0; ry_reg<1>(a, m0.x, m0.y);   // RY(0, w34+w36)
        const float2 m6 = s_mry6; ry_reg<8>(a, m6.x, m6.y);   // RY(6, w35+w37)
    }

    // ---- conv3 ----
    cx_rr<1, 8>(a);            // (0,6)
    {   // RZ(0, w38) on register bit 0
        const float cz = s_wc[38], sz = s_ws[38];
        #pragma unroll
        for (int r = 0; r < 16; ++r) {
            const float d = (r & 1) ? sz : -sz;
            const float2 v = a[r];
            a[r] = { cz * v.x - d * v.y, cz * v.y + d * v.x };
        }
    }
    // RZ(6, w39) dropped.

    // ---- pool3 CRX(6,0) ----
    crx_rr<8, 1>(a, s_wc[40], s_ws[40]);
    // Final RY(0, w41) folded into measurement (Bloch rotation below).

    // ---- <X>,<Y>,<Z> on qubit 0 (register bit 0), pre-RY(w41) ----
    float zr = 0.f, zi = 0.f, ez = 0.f;
    #pragma unroll
    for (int r0 = 0; r0 < 16; r0 += 2) {
        float2 a0 = a[r0], a1 = a[r0 + 1];
        zr += a0.x * a1.x + a0.y * a1.y;
        zi += a0.x * a1.y - a0.y * a1.x;
        ez += a0.x * a0.x + a0.y * a0.y - a1.x * a1.x - a1.y * a1.y;
    }
    #pragma unroll
    for (int off = 16; off; off >>= 1) {
        zr += __shfl_xor_sync(FULL_MASK, zr, off);
        zi += __shfl_xor_sync(FULL_MASK, zi, off);
        ez += __shfl_xor_sync(FULL_MASK, ez, off);
    }

    // ---- fused FC: lanes 0..ncls-1 stage class partials in smem ----
    if (lane < ncls) {
        // Bloch rotation for RY(w41): ex' = c*ex + s*ez ; ez' = -s*ex + c*ez ; ey' = ey
        const float2 m = s_m41;
        const float ex0 = 2.f * zr, ey = 2.f * zi;
        const float ex = m.x * ex0 + m.y * ez;
        const float ezf = -m.y * ex0 + m.x * ez;
        const float* wrow = fc_w + lane * K + rem * 3;
        const float partial = ex * wrow[0] + ey * wrow[1] + ezf * wrow[2];
        atomicAdd(&s_acc[lane], partial);
    }
    __syncthreads();

    // ---- stage into device scratch, then last-finishing block finalizes ----
    if (tid < ncls) {
        const int b_blk = (blockIdx.x << 2) / 676;   // b is block-uniform
        atomicAdd(&g_stage[b_blk * ncls + tid], s_acc[tid]);
        __threadfence();
    }
    __syncthreads();
    if (tid == 0) s_rank = atomicAdd(&g_count, 1);
    __syncthreads();

    if (s_rank == nblocks - 1) {   // all other blocks' stage atomics are visible
        __threadfence();
        for (int i = tid; i < nout; i += blockDim.x) {
            out[i] = g_stage[i] + fc_b[i % ncls];
            g_stage[i] = 0.f;      // restore invariant for next launch/replay
        }
        if (tid == 0) g_count = 0;
    }
}

// ============================================================================
extern "C" void kernel_launch(void* const* d_in, const int* in_sizes, int n_in,
                              void* d_out, int out_size) {
    const float* x    = (const float*)d_in[0];   // (B,1,28,28)
    const float* w    = (const float*)d_in[1];   // (42,)
    const float* fc_w = (const float*)d_in[2];   // (ncls, K)
    const float* fc_b = (const float*)d_in[3];   // (ncls,)
    float* out = (float*)d_out;

    const int B      = in_sizes[0] / (28 * 28);
    const int npatch = B * 26 * 26;              // 676 % 4 == 0 -> exact grid
    const int ncls   = in_sizes[3];
    const int K      = in_sizes[2] / ncls;
    const int nblocks = npatch / 4;

    qcnn_kernel<<<nblocks, 128>>>(x, w, fc_w, fc_b, out, K, ncls, nblocks, B * ncls);
}